// round 11
// baseline (speedup 1.0000x reference)
#include <cuda_runtime.h>
#include <cstdint>

#define BB    256
#define LL    512
#define DD    64
#define NID   10000
#define TROWS 8      // g-table rows; counts >= 8 take the (never-hit) uniform cold path

// ---------------------------------------------------------------------------
// One CTA per batch. Packed smem histogram (lo16 = count of id in src seq,
// hi16 = count in dst seq). 8x64 g-table built concurrently with the atomics.
// Store: pass A writes the register-cached mode row g(1)+g(0) to every row
// (pure STG.128, no loads); pass B overwrites the ~10% exception rows from a
// compacted list. Mode row is identical for src (1,0) and dst (0,1) roles.
// ---------------------------------------------------------------------------
__global__ void __launch_bounds__(512) fused_encode(
        const int* __restrict__ src,
        const int* __restrict__ dst,
        const float* __restrict__ W1,
        const float* __restrict__ b1,
        const float* __restrict__ W2,
        const float* __restrict__ b2,
        float* __restrict__ out) {
    __shared__ __align__(16) uint32_t hist[NID];          // 40000 B
    __shared__ __align__(16) float    g8[TROWS * DD];     //  2048 B
    __shared__ __align__(16) uint32_t exc[2 * LL];        //  4096 B
    __shared__ float w1s[DD], b1s[DD], b2s[DD];           //   768 B
    __shared__ uint32_t maxc, nexc;

    const int t = threadIdx.x;
    const int b = blockIdx.x;

    // ---- P0: zero histogram (128-bit), stage params, load ids ----
    const uint4 z = make_uint4(0u, 0u, 0u, 0u);
    #pragma unroll
    for (int i = t; i < NID / 4; i += 512) ((uint4*)hist)[i] = z;
    if (t < DD)            w1s[t]          = W1[t];
    else if (t < 2 * DD)   b1s[t - DD]     = b1[t - DD];
    else if (t < 3 * DD)   b2s[t - 2 * DD] = b2[t - 2 * DD];
    if (t == 0) { maxc = 0u; nexc = 0u; }

    const int sid = src[b * LL + t];
    const int did = dst[b * LL + t];
    __syncthreads();

    // ---- P1: packed dual histogram + (concurrently) 8x64 g-table build ----
    atomicAdd(&hist[sid], 1u);
    atomicAdd(&hist[did], 0x10000u);
    {
        const int a = t >> 6, e = t & 63;      // 512 threads = 8 rows x 64 cols
        const float fa = (float)a;
        float s = b2s[e];
        const float4* w2r4 = (const float4*)(W2 + e * DD);
        #pragma unroll 4
        for (int j = 0; j < 16; ++j) {
            const float4 w4 = __ldg(&w2r4[j]);
            const int d = j * 4;
            const float h0 = fmaxf(fmaf(fa, w1s[d + 0], b1s[d + 0]), 0.f);
            const float h1 = fmaxf(fmaf(fa, w1s[d + 1], b1s[d + 1]), 0.f);
            const float h2 = fmaxf(fmaf(fa, w1s[d + 2], b1s[d + 2]), 0.f);
            const float h3 = fmaxf(fmaf(fa, w1s[d + 3], b1s[d + 3]), 0.f);
            s = fmaf(h0, w4.x, s);
            s = fmaf(h1, w4.y, s);
            s = fmaf(h2, w4.z, s);
            s = fmaf(h3, w4.w, s);
        }
        g8[t] = s;
    }
    __syncthreads();

    // ---- P2: gather counts; push non-mode rows as exceptions; max-reduce ----
    const uint32_t hs = sid ? hist[sid] : 0u;   // padding id 0 -> (0,0)
    const uint32_t hd = did ? hist[did] : 0u;
    // exception word: row[0:9) | role[9] | a0[10:20) | a1[20:30)
    if (hs != 1u) {          // src mode is (a0,a1) = (1,0)
        const uint32_t i = atomicAdd(&nexc, 1u);
        exc[i] = (uint32_t)t | ((hs & 0xFFFFu) << 10) | ((hs >> 16) << 20);
    }
    if (hd != 0x10000u) {    // dst mode is (a0,a1) = (0,1)
        const uint32_t i = atomicAdd(&nexc, 1u);
        exc[i] = (uint32_t)t | (1u << 9) | ((hd & 0xFFFFu) << 10) | ((hd >> 16) << 20);
    }
    uint32_t m = max(max(hs & 0xFFFFu, hs >> 16), max(hd & 0xFFFFu, hd >> 16));
    m = __reduce_max_sync(0xFFFFFFFFu, m);
    if ((t & 31) == 0) atomicMax(&maxc, m);
    __syncthreads();

    const int lane = t & 15;
    const float4* __restrict__ G4 = (const float4*)g8;
    float4* __restrict__ osrc = (float4*)(out + (size_t)b * LL * DD);
    float4* __restrict__ odst = (float4*)(out + ((size_t)BB + b) * LL * DD);

    if (maxc < TROWS) {
        // ---- P3a: mode row everywhere. g(1)+g(0) == g(0)+g(1) bit-exactly.
        const float4 t1 = G4[16 + lane];
        const float4 t0 = G4[lane];
        float4 wm;
        wm.x = t1.x + t0.x; wm.y = t1.y + t0.y;
        wm.z = t1.z + t0.z; wm.w = t1.w + t0.w;
        #pragma unroll
        for (int r = (t >> 4); r < LL; r += 32) {
            osrc[r * 16 + lane] = wm;
            odst[r * 16 + lane] = wm;
        }
        __syncthreads();   // order pass-A stores before pass-B overwrites

        // ---- P3b: overwrite exception rows (16 lanes per entry) ----
        const uint32_t n = nexc;
        for (uint32_t i = (uint32_t)(t >> 4); i < n; i += 32) {
            const uint32_t e   = exc[i];
            const uint32_t row = e & 511u;
            const uint32_t a0  = (e >> 10) & 1023u;
            const uint32_t a1  = e >> 20;
            const float4 v0 = G4[a0 * 16 + lane];
            const float4 v1 = G4[a1 * 16 + lane];
            float4 w;
            w.x = v0.x + v1.x; w.y = v0.y + v1.y;
            w.z = v0.z + v1.z; w.w = v0.w + v1.w;
            float4* o = (e & (1u << 9)) ? odst : osrc;
            o[row * 16 + lane] = w;
        }
    } else {
        // ---- cold path (CTA-uniform, never taken): direct compute from the
        // intact histogram, reloading ids per row. ----
        for (int r = (t >> 4); r < LL; r += 32) {
            const int sid2 = src[b * LL + r];
            const int did2 = dst[b * LL + r];
            const uint32_t csr = sid2 ? hist[sid2] : 0u;
            const uint32_t cdr = did2 ? hist[did2] : 0u;
            const float sa0 = (float)(csr & 0xFFFFu), sa1 = (float)(csr >> 16);
            const float da0 = (float)(cdr & 0xFFFFu), da1 = (float)(cdr >> 16);
            float4 accs, accd;
            accs.x = 2.f * b2s[lane * 4 + 0]; accd.x = accs.x;
            accs.y = 2.f * b2s[lane * 4 + 1]; accd.y = accs.y;
            accs.z = 2.f * b2s[lane * 4 + 2]; accd.z = accs.z;
            accs.w = 2.f * b2s[lane * 4 + 3]; accd.w = accs.w;
            for (int d = 0; d < DD; ++d) {
                const float hss = fmaxf(fmaf(sa0, w1s[d], b1s[d]), 0.f)
                                + fmaxf(fmaf(sa1, w1s[d], b1s[d]), 0.f);
                const float hdd = fmaxf(fmaf(da0, w1s[d], b1s[d]), 0.f)
                                + fmaxf(fmaf(da1, w1s[d], b1s[d]), 0.f);
                accs.x = fmaf(hss, __ldg(&W2[(lane*4+0)*DD + d]), accs.x);
                accs.y = fmaf(hss, __ldg(&W2[(lane*4+1)*DD + d]), accs.y);
                accs.z = fmaf(hss, __ldg(&W2[(lane*4+2)*DD + d]), accs.z);
                accs.w = fmaf(hss, __ldg(&W2[(lane*4+3)*DD + d]), accs.w);
                accd.x = fmaf(hdd, __ldg(&W2[(lane*4+0)*DD + d]), accd.x);
                accd.y = fmaf(hdd, __ldg(&W2[(lane*4+1)*DD + d]), accd.y);
                accd.z = fmaf(hdd, __ldg(&W2[(lane*4+2)*DD + d]), accd.z);
                accd.w = fmaf(hdd, __ldg(&W2[(lane*4+3)*DD + d]), accd.w);
            }
            osrc[r * 16 + lane] = accs;
            odst[r * 16 + lane] = accd;
        }
    }
}

// ---------------------------------------------------------------------------
// Inputs: 0 src_ids, 1 dst_ids, 2 W1(D,1), 3 b1(D), 4 W2(D,D), 5 b2(D)
// Output: [src_feat | dst_feat], each B*L*D f32.
// ---------------------------------------------------------------------------
extern "C" void kernel_launch(void* const* d_in, const int* in_sizes, int n_in,
                              void* d_out, int out_size) {
    const int*   src = (const int*)d_in[0];
    const int*   dst = (const int*)d_in[1];
    const float* W1  = (const float*)d_in[2];
    const float* b1  = (const float*)d_in[3];
    const float* W2  = (const float*)d_in[4];
    const float* b2  = (const float*)d_in[5];
    float* out = (float*)d_out;

    fused_encode<<<BB, 512>>>(src, dst, W1, b1, W2, b2, out);
}